// round 7
// baseline (speedup 1.0000x reference)
#include <cuda_runtime.h>
#include <cstdint>

#define LL 1024
#define DD 128
#define BQ 32
#define NT 256

#define S_FLOATS   (BQ * LL)        // 32768 floats = 128 KB
#define TILE_WORDS (128 * 132)      // 16896 floats = 66 KB (K: [128][33 f4]; V: [128][130+] words)
#define Q_FLOATS   (BQ * DD)        // 4096 floats = 16 KB
#define SMEM_BYTES ((S_FLOATS + TILE_WORDS + Q_FLOATS) * 4)   // 215040

typedef unsigned long long ull;

__device__ __forceinline__ ull pk2(float lo, float hi) {
    ull r; asm("mov.b64 %0, {%1, %2};" : "=l"(r) : "f"(lo), "f"(hi)); return r;
}
__device__ __forceinline__ float2 up2(ull v) {
    float2 r; asm("mov.b64 {%0, %1}, %2;" : "=f"(r.x), "=f"(r.y) : "l"(v)); return r;
}
__device__ __forceinline__ void fma2(ull &a, ull x, ull y) {
    asm("fma.rn.f32x2 %0, %1, %2, %0;" : "+l"(a) : "l"(x), "l"(y));
}

__global__ __launch_bounds__(NT, 1)
void attn_neg_kernel(const float* __restrict__ Qg, const float* __restrict__ Kg,
                     const float* __restrict__ Vg, const float* __restrict__ scp,
                     const float* __restrict__ kg, float* __restrict__ outg)
{
    extern __shared__ float smem[];
    float*  S   = smem;                          // [BQ][LL]
    float*  Tl  = smem + S_FLOATS;               // tile region (K then V)
    float4* Qs4 = (float4*)(smem + S_FLOATS + TILE_WORDS);  // [BQ][32]

    const int tid = threadIdx.x, warp = tid >> 5, lane = tid & 31;
    const int b = blockIdx.y, q0 = blockIdx.x * BQ;
    const float negscale = -scp[0];

    // ---- stage Q [32q][32 f4 of d] ----
    {
        const float4* Qg4 = (const float4*)(Qg + ((size_t)b * LL + q0) * DD);
        #pragma unroll
        for (int i = 0; i < 4; i++) Qs4[tid + NT * i] = Qg4[tid + NT * i];
    }

    // ============ Phase 1: S = -scale * Q @ K^T  (d-packed fma2, Gq=8) ============
    // warp w: q rows (w>>1)*8..+7 ; k-half (w&1)*64 ; lane owns k0=half+lane, k0+32
    {
        const float4* Kgl = (const float4*)(Kg + (size_t)b * LL * DD);
        float4* Kt4 = (float4*)Tl;               // [128 k][33 f4]
        const int qg = warp >> 1;
        const int k0 = (warp & 1) * 64 + lane;

        float4 buf[16];
        #pragma unroll
        for (int i = 0; i < 16; i++) buf[i] = Kgl[tid + NT * i];

        for (int kt = 0; kt < 8; kt++) {
            __syncthreads();
            #pragma unroll
            for (int i = 0; i < 16; i++) {
                int idx = tid + NT * i;
                Kt4[(idx >> 5) * 33 + (idx & 31)] = buf[i];
            }
            __syncthreads();
            if (kt < 7) {
                #pragma unroll
                for (int i = 0; i < 16; i++)
                    buf[i] = Kgl[(kt + 1) * 4096 + tid + NT * i];
            }

            ull acc[8][2];
            #pragma unroll
            for (int i = 0; i < 8; i++) { acc[i][0] = 0ull; acc[i][1] = 0ull; }

            #pragma unroll 4
            for (int d4 = 0; d4 < 32; d4++) {
                float4 ka = Kt4[k0 * 33 + d4];
                float4 kb = Kt4[(k0 + 32) * 33 + d4];
                ull ka01 = pk2(ka.x, ka.y), ka23 = pk2(ka.z, ka.w);  // adjacent regs: no real MOV
                ull kb01 = pk2(kb.x, kb.y), kb23 = pk2(kb.z, kb.w);
                #pragma unroll
                for (int i = 0; i < 8; i++) {
                    float4 qv = Qs4[(qg * 8 + i) * 32 + d4];         // broadcast
                    ull q01 = pk2(qv.x, qv.y), q23 = pk2(qv.z, qv.w);
                    fma2(acc[i][0], q01, ka01);  fma2(acc[i][0], q23, ka23);
                    fma2(acc[i][1], q01, kb01);  fma2(acc[i][1], q23, kb23);
                }
            }
            #pragma unroll
            for (int i = 0; i < 8; i++) {
                float2 a = up2(acc[i][0]), c = up2(acc[i][1]);
                float* sp = S + (qg * 8 + i) * LL + kt * 128;
                sp[k0]      = (a.x + a.y) * negscale;
                sp[k0 + 32] = (c.x + c.y) * negscale;
            }
        }
    }
    __syncthreads();

    // ============ Phase 2: beta = softmax(-softmax(S) * kg)  (float4) ============
    // t = -p*kg in [-1,0] -> second max pass skipped (m2 = 0).
    #pragma unroll 1
    for (int r = 0; r < 4; r++) {
        const int q = warp * 4 + r;
        float4* Srow4 = (float4*)(S + q * LL);
        const float4* kg4 = (const float4*)(kg + ((size_t)b * LL + q0 + q) * LL);

        float m1 = -1e30f;
        #pragma unroll
        for (int i = 0; i < 8; i++) {
            float4 s = Srow4[lane + 32 * i];
            m1 = fmaxf(m1, fmaxf(fmaxf(s.x, s.y), fmaxf(s.z, s.w)));
        }
        #pragma unroll
        for (int o = 16; o; o >>= 1) m1 = fmaxf(m1, __shfl_xor_sync(~0u, m1, o));

        float z1 = 0.f;
        #pragma unroll
        for (int i = 0; i < 8; i++) {
            float4 s = Srow4[lane + 32 * i];
            z1 += __expf(s.x - m1) + __expf(s.y - m1) + __expf(s.z - m1) + __expf(s.w - m1);
        }
        #pragma unroll
        for (int o = 16; o; o >>= 1) z1 += __shfl_xor_sync(~0u, z1, o);
        const float inv1 = 1.0f / z1;

        float z2 = 0.f;
        #pragma unroll
        for (int i = 0; i < 8; i++) {
            float4 s = Srow4[lane + 32 * i];
            float4 g = kg4[lane + 32 * i];
            float4 e;
            e.x = __expf(-__expf(s.x - m1) * inv1 * g.x);
            e.y = __expf(-__expf(s.y - m1) * inv1 * g.y);
            e.z = __expf(-__expf(s.z - m1) * inv1 * g.z);
            e.w = __expf(-__expf(s.w - m1) * inv1 * g.w);
            Srow4[lane + 32 * i] = e;
            z2 += e.x + e.y + e.z + e.w;
        }
        #pragma unroll
        for (int o = 16; o; o >>= 1) z2 += __shfl_xor_sync(~0u, z2, o);
        const float inv2 = 1.0f / z2;
        #pragma unroll
        for (int i = 0; i < 8; i++) {
            float4 e = Srow4[lane + 32 * i];
            e.x *= inv2; e.y *= inv2; e.z *= inv2; e.w *= inv2;
            Srow4[lane + 32 * i] = e;
        }
    }

    // ============ Phase 3: out = beta @ V  (k-pair packed fma2, Vt d-major) ============
    // V tile KT=64, loaded lane-per-k (strided LDG, L2-resident), stored transposed:
    // Vt[d][k] word layout, row stride 130 words (f2-aligned, conflict-free).
    // warp w: q rows (w>>1)*8..+7 ; d-half (w&1)*64 ; lane owns dA=half+lane, dA+32.
    {
        const float4* Vgl = (const float4*)(Vg + (size_t)b * LL * DD);
        const int kLane  = (warp & 1) * 32 + lane;   // load-role: lane = k within tile
        const int d4base = (warp >> 1) * 8;          // load-role: 8 d4 columns
        const int qg = warp >> 1;
        const int dA = (warp & 1) * 64 + lane;       // compute-role
        const int dB = dA + 32;

        float4 vbuf[8];
        #pragma unroll
        for (int c = 0; c < 8; c++) vbuf[c] = Vgl[kLane * 32 + d4base + c];

        ull acc[8][2];
        #pragma unroll
        for (int i = 0; i < 8; i++) { acc[i][0] = 0ull; acc[i][1] = 0ull; }

        for (int vt = 0; vt < 16; vt++) {
            __syncthreads();
            #pragma unroll
            for (int c = 0; c < 8; c++) {            // transpose store, conflict-free
                float4 v = vbuf[c];
                int d = (d4base + c) * 4;
                Tl[(d + 0) * 130 + kLane] = v.x;
                Tl[(d + 1) * 130 + kLane] = v.y;
                Tl[(d + 2) * 130 + kLane] = v.z;
                Tl[(d + 3) * 130 + kLane] = v.w;
            }
            __syncthreads();
            if (vt < 15) {
                #pragma unroll
                for (int c = 0; c < 8; c++)
                    vbuf[c] = Vgl[((vt + 1) * 64 + kLane) * 32 + d4base + c];
            }

            const float2* Vt2 = (const float2*)Tl;   // f2 row stride 65
            #pragma unroll 2
            for (int kk = 0; kk < 16; kk++) {        // 4 k per kk
                float2 a0 = Vt2[dA * 65 + 2 * kk], a1 = Vt2[dA * 65 + 2 * kk + 1];
                float2 b0 = Vt2[dB * 65 + 2 * kk], b1 = Vt2[dB * 65 + 2 * kk + 1];
                ull uA0 = pk2(a0.x, a0.y), uA1 = pk2(a1.x, a1.y);
                ull uB0 = pk2(b0.x, b0.y), uB1 = pk2(b1.x, b1.y);
                #pragma unroll
                for (int i = 0; i < 8; i++) {
                    float4 bq = ((const float4*)(S + (qg * 8 + i) * LL + vt * 64))[kk]; // broadcast
                    ull p01 = pk2(bq.x, bq.y), p23 = pk2(bq.z, bq.w);
                    fma2(acc[i][0], p01, uA0);  fma2(acc[i][0], p23, uA1);
                    fma2(acc[i][1], p01, uB0);  fma2(acc[i][1], p23, uB1);
                }
            }
        }

        float* outp = outg + ((size_t)b * LL + q0) * DD;
        #pragma unroll
        for (int i = 0; i < 8; i++) {
            float2 a = up2(acc[i][0]), c = up2(acc[i][1]);
            outp[(qg * 8 + i) * DD + dA] = a.x + a.y;
            outp[(qg * 8 + i) * DD + dB] = c.x + c.y;
        }
    }
}

extern "C" void kernel_launch(void* const* d_in, const int* in_sizes, int n_in,
                              void* d_out, int out_size) {
    const float* Q  = (const float*)d_in[0];
    const float* K  = (const float*)d_in[1];
    const float* V  = (const float*)d_in[2];
    const float* sc = (const float*)d_in[3];
    const float* kg = (const float*)d_in[4];
    float* out = (float*)d_out;
    (void)in_sizes; (void)n_in; (void)out_size;

    cudaFuncSetAttribute(attn_neg_kernel,
                         cudaFuncAttributeMaxDynamicSharedMemorySize, SMEM_BYTES);
    dim3 grid(LL / BQ, 32);
    attn_neg_kernel<<<grid, NT, SMEM_BYTES>>>(Q, K, V, sc, kg, out);
}